// round 13
// baseline (speedup 1.0000x reference)
#include <cuda_runtime.h>
#include <cuda_bf16.h>

// FastMMGCN: LightGCN 3-layer propagation, pull-based CSR, fused epilogues.
//
// Inputs (metadata order):
//   d_in[0] user_table  f32 [100000, 64]
//   d_in[1] item_table  f32 [50000, 64]
//   d_in[2] user_idx    i32 [2000000]
//   d_in[3] item_idx    i32 [2000000]
//   d_in[4] num_layers  i32 scalar (device-resident)
// Output: f32 [150000, 64] = concat(acc_u, acc_i) / (num_layers+1)
//
// R10 changes vs R9 (487.5us): scale folded into last pull layer; last-layer
// nxt write skipped; layer 0 reads input tables directly (init only fills out);
// norm fused into scatter (g_norm deleted); cursor init fused into scan3.
//
// NOTE: __device__ globals must NEVER be passed as kernel arguments from host
// code (host shadow address != device address; ATS makes it silently readable).

#define NUSERS 100000
#define NITEMS 50000
#define NTOT   (NUSERS + NITEMS)
#define MAXE   2000000
#define EMB_D  64
#define MAX_LAYERS 4

#define NU4 (NUSERS * EMB_D / 4)
#define NI4 (NITEMS * EMB_D / 4)
#define NT4 (NU4 + NI4)

// ---- static device scratch (no allocation allowed) ----
__device__ int       g_deg_u[NUSERS];
__device__ int       g_deg_i[NITEMS];
__device__ int       g_offs_u[NUSERS + 1];
__device__ int       g_offs_i[NITEMS + 1];
__device__ int       g_cur_u[NUSERS];
__device__ int       g_cur_i[NITEMS];
__device__ int       g_part_u[128];
__device__ int       g_part_i[128];
__device__ long long g_ent_u[MAXE];   // packed {norm(f32)<<32 | item_idx}
__device__ long long g_ent_i[MAXE];   // packed {norm(f32)<<32 | user_idx}
__device__ float4    g_ua[NU4];       // user cur ping (written at layer 1)
__device__ float4    g_ub[NU4];       // user cur pong (written at layer 0)
__device__ float4    g_ia[NI4];
__device__ float4    g_ib[NI4];

__device__ __forceinline__ long long pack_ent(int s, float w) {
    return ((long long)__float_as_int(w) << 32) | (unsigned int)s;
}

// ---------------------------------------------------------------------------
__global__ void __launch_bounds__(256) zero_deg_kernel() {
    int i = blockIdx.x * blockDim.x + threadIdx.x;
    if (i < NUSERS) g_deg_u[i] = 0;
    if (i < NITEMS) g_deg_i[i] = 0;
}

__global__ void __launch_bounds__(256) count_deg_kernel(
    const int* __restrict__ uidx, const int* __restrict__ iidx, int E) {
    int e = blockIdx.x * blockDim.x + threadIdx.x;
    if (e >= E) return;
    atomicAdd(&g_deg_u[uidx[e]], 1);
    atomicAdd(&g_deg_i[iidx[e]], 1);
}

// ---- exclusive scan (3-phase); which: 0 = user arrays, 1 = item arrays ----
__global__ void __launch_bounds__(1024) scan1_kernel(int which) {
    const int* __restrict__ deg = which ? g_deg_i : g_deg_u;
    int*  offs = which ? g_offs_i : g_offs_u;
    int*  part = which ? g_part_i : g_part_u;
    int   n    = which ? NITEMS   : NUSERS;

    __shared__ int sh[1024];
    int tid = threadIdx.x;
    int i = blockIdx.x * 1024 + tid;
    int v = (i < n) ? deg[i] : 0;
    sh[tid] = v;
    __syncthreads();
    for (int s = 1; s < 1024; s <<= 1) {
        int t = (tid >= s) ? sh[tid - s] : 0;
        __syncthreads();
        sh[tid] += t;
        __syncthreads();
    }
    if (i < n) offs[i] = sh[tid] - v;             // block-local exclusive
    if (tid == 1023) part[blockIdx.x] = sh[tid];  // block total
}

__global__ void __launch_bounds__(1024) scan2_kernel(int which, int nb) {
    int* part = which ? g_part_i : g_part_u;
    int* offs = which ? g_offs_i : g_offs_u;
    int  n    = which ? NITEMS   : NUSERS;

    __shared__ int sh[1024];
    int tid = threadIdx.x;
    int v = (tid < nb) ? part[tid] : 0;
    sh[tid] = v;
    __syncthreads();
    for (int s = 1; s < 1024; s <<= 1) {
        int t = (tid >= s) ? sh[tid - s] : 0;
        __syncthreads();
        sh[tid] += t;
        __syncthreads();
    }
    if (tid < nb) part[tid] = sh[tid] - v;   // exclusive block prefix
    if (tid == 1023) offs[n] = sh[1023];     // grand total
}

// scan3 also initializes the scatter cursors from the final offsets.
__global__ void __launch_bounds__(1024) scan3_kernel(int which) {
    const int* __restrict__ part = which ? g_part_i : g_part_u;
    int* offs = which ? g_offs_i : g_offs_u;
    int* cur  = which ? g_cur_i  : g_cur_u;
    int  n    = which ? NITEMS   : NUSERS;
    int i = blockIdx.x * 1024 + threadIdx.x;
    if (i < n) {
        int o = offs[i] + part[blockIdx.x];
        offs[i] = o;
        cur[i]  = o;
    }
}

// norm fused: w = rsqrt(deg_u * deg_i) computed here (deg arrays are ~600KB,
// L2-resident; saves the g_norm array round-trip entirely).
__global__ void __launch_bounds__(256) scatter_csr_kernel(
    const int* __restrict__ uidx, const int* __restrict__ iidx, int E) {
    int e = blockIdx.x * blockDim.x + threadIdx.x;
    if (e >= E) return;
    int u = uidx[e], it = iidx[e];
    int du = g_deg_u[u];  if (du < 1) du = 1;
    int di = g_deg_i[it]; if (di < 1) di = 1;
    float w = rsqrtf((float)du * (float)di);
    int pu = atomicAdd(&g_cur_u[u], 1);
    g_ent_u[pu] = pack_ent(it, w);
    int pi = atomicAdd(&g_cur_i[it], 1);
    g_ent_i[pi] = pack_ent(u, w);
}

// out = concat(tables). Layer 0 reads sources straight from the input tables,
// so no ping-buffer copy is needed here.
__global__ void __launch_bounds__(256) init_emb_kernel(
    const float4* __restrict__ ut, const float4* __restrict__ itb,
    float4* __restrict__ out) {
    int i = blockIdx.x * blockDim.x + threadIdx.x;
    if (i < NU4)       out[i] = ut[i];
    else if (i < NT4)  out[i] = itb[i - NU4];
}

// One warp per destination node; lane owns 2 floats of the 64-wide row.
// next[node] = sum_e w_e * src[neighbor_e]; out[node] += next.
// Last layer: skip next-write, apply final 1/(nl+1) scale to out.
__global__ void __launch_bounds__(256) pull_kernel(
    const int* __restrict__ nl, int layer, int flip, float* __restrict__ out,
    const float* __restrict__ ut, const float* __restrict__ itb) {
    int n = *nl;
    if (layer >= n) return;
    bool last = (layer == n - 1);
    float s = last ? (1.0f / (float)(n + 1)) : 1.0f;

    int gw   = (blockIdx.x * blockDim.x + threadIdx.x) >> 5;
    int lane = threadIdx.x & 31;
    if (gw >= NTOT) return;

    const float* __restrict__ src;
    float* nxt;
    const long long* __restrict__ ent;
    int beg, end;
    if (gw < NUSERS) {
        // users aggregate item rows
        src = (layer == 0) ? itb : (const float*)(flip ? g_ib : g_ia);
        nxt = (float*)(flip ? g_ua : g_ub) + gw * EMB_D;
        ent = g_ent_u;
        beg = g_offs_u[gw];
        end = g_offs_u[gw + 1];
    } else {
        int it = gw - NUSERS;
        // items aggregate user rows
        src = (layer == 0) ? ut : (const float*)(flip ? g_ub : g_ua);
        nxt = (float*)(flip ? g_ia : g_ib) + it * EMB_D;
        ent = g_ent_i;
        beg = g_offs_i[it];
        end = g_offs_i[it + 1];
    }
    float* orow = out + (long)gw * EMB_D;               // concat layout == gw

    float accx = 0.f, accy = 0.f;
    for (int base = beg; base < end; base += 32) {
        int idx = base + lane;
        long long mine = (idx < end) ? ent[idx] : 0;
        int cnt = end - base; if (cnt > 32) cnt = 32;
        #pragma unroll 4
        for (int j = 0; j < cnt; j++) {
            long long e = __shfl_sync(0xffffffffu, mine, j);
            int   si = (int)(e & 0xffffffffLL);
            float w  = __int_as_float((int)(e >> 32));
            float2 v = *reinterpret_cast<const float2*>(src + si * EMB_D + lane * 2);
            accx = fmaf(w, v.x, accx);
            accy = fmaf(w, v.y, accy);
        }
    }

    if (!last)
        *reinterpret_cast<float2*>(nxt + lane * 2) = make_float2(accx, accy);

    float2* op = reinterpret_cast<float2*>(orow + lane * 2);
    float2 o = *op;
    o.x = (o.x + accx) * s;
    o.y = (o.y + accy) * s;
    *op = o;
}

// ---------------------------------------------------------------------------
extern "C" void kernel_launch(void* const* d_in, const int* in_sizes, int n_in,
                              void* d_out, int out_size) {
    const float* ut  = (const float*)d_in[0];
    const float* itb = (const float*)d_in[1];
    const int* uidx  = (const int*)d_in[2];
    const int* iidx  = (const int*)d_in[3];
    const int* nl    = (const int*)d_in[4];
    float* out = (float*)d_out;

    int E = in_sizes[2];
    if (E > MAXE) E = MAXE;

    const int T = 256;
    int deg_blocks  = (NUSERS + T - 1) / T;
    int edge_blocks = (E + T - 1) / T;
    int emb_blocks  = (NT4 + T - 1) / T;
    int pull_blocks = (NTOT * 32 + T - 1) / T;
    int ub = (NUSERS + 1023) / 1024;   // 98
    int ib = (NITEMS + 1023) / 1024;   // 49

    // degrees
    zero_deg_kernel<<<deg_blocks, T>>>();
    count_deg_kernel<<<edge_blocks, T>>>(uidx, iidx, E);

    // CSR build (globals selected inside device code; norm fused into scatter)
    scan1_kernel<<<ub, 1024>>>(0);
    scan1_kernel<<<ib, 1024>>>(1);
    scan2_kernel<<<1, 1024>>>(0, ub);
    scan2_kernel<<<1, 1024>>>(1, ib);
    scan3_kernel<<<ub, 1024>>>(0);     // also inits cursors
    scan3_kernel<<<ib, 1024>>>(1);
    scatter_csr_kernel<<<edge_blocks, T>>>(uidx, iidx, E);

    // out = concat(tables); layer 0 reads tables directly
    init_emb_kernel<<<emb_blocks, T>>>((const float4*)ut, (const float4*)itb,
                                       (float4*)out);

    // propagation; final scale folded into last active layer
    for (int l = 0; l < MAX_LAYERS; l++) {
        pull_kernel<<<pull_blocks, T>>>(nl, l, l & 1, out, ut, itb);
    }
}